// round 12
// baseline (speedup 1.0000x reference)
#include <cuda_runtime.h>
#include <cuda_bf16.h>

// ChannelPolyLayer: out[b,o,x,y] = sum_c coeffs[b,o,c] * prod_v img[b,v,x,y]^powers[c,v]
// DEGREE=3, NUM_VARS=3, NUM_OUT=3, NUM_COEFFS=20, BATCH=16, H=W=512.
//
// Monomial order from _generate_powers(3,3):
//  0:1  1:v0  2:v1  3:v2  4:v0^2  5:v0v1  6:v0v2  7:v1^2  8:v1v2  9:v2^2
// 10:v0^3 11:v0^2v1 12:v0^2v2 13:v0v1^2 14:v0v1v2 15:v0v2^2
// 16:v1^3 17:v1^2v2 18:v1v2^2 19:v2^3
//
// Nested Horner, packed fma.rn.f32x2 (19 per output per pixel-pair).
// R12 = R11 persistent one-wave shape (wall ~= ncu-0.2us, vs +2.1us for
// multi-wave grids) + pointer-increment addressing: one load ptr + one
// store ptr bumped by STRIDE per iteration, all 12 accesses at
// compile-time immediate offsets (<= 2.5MB, inside LDG/STG +-8MB range).
// Kills the 7.2% alu pipe (index IMADs) measured in R11. MLP=6 continuous
// register prefetch unchanged; plain STG (.cs proven neutral in R11).

#define HW_PIX (512 * 512)
#define PLANE4 (HW_PIX / 4)       // 65536 float4s per channel plane
#define HALF4  (PLANE4 / 2)       // 32768 items; item j covers float4 j, j+HALF4
#define NBATCH 16
#define NCOEF  20
#define TPB    256
#define CTAS_X 18                 // 18*16 = 288 CTAs ~= one wave at 2 CTAs/SM
#define STRIDE (CTAS_X * TPB)     // 4608

typedef unsigned long long ull;

__device__ __forceinline__ ull ffma2(ull a, ull b, ull c) {
    ull d;
    asm("fma.rn.f32x2 %0, %1, %2, %3;" : "=l"(d) : "l"(a), "l"(b), "l"(c));
    return d;
}

// Horner over a packed pair of pixels. c[] are {coeff,coeff} splat pairs.
__device__ __forceinline__ ull horner2(ull v0, ull v1, ull v2,
                                       const ull* __restrict__ c) {
    ull pA = ffma2(c[16], v1, c[7]);
    pA = ffma2(v1, pA, c[2]);
    pA = ffma2(v1, pA, c[0]);
    ull pB = ffma2(c[17], v1, c[8]);
    pB = ffma2(v1, pB, c[3]);
    ull pC = ffma2(c[18], v1, c[9]);
    ull C0 = ffma2(c[19], v2, pC);
    C0 = ffma2(C0, v2, pB);
    C0 = ffma2(C0, v2, pA);
    ull qA = ffma2(c[13], v1, c[5]);
    qA = ffma2(v1, qA, c[1]);
    ull qB = ffma2(c[14], v1, c[6]);
    ull C1 = ffma2(c[15], v2, qB);
    C1 = ffma2(C1, v2, qA);
    ull C2 = ffma2(c[11], v1, c[4]);
    C2 = ffma2(c[12], v2, C2);
    ull r = ffma2(c[10], v0, C2);
    r = ffma2(r, v0, C1);
    r = ffma2(r, v0, C0);
    return r;
}

__global__ __launch_bounds__(TPB, 2) void channel_poly_kernel(
    const float* __restrict__ img,     // (B, 3, H, W)
    const float* __restrict__ coeffs,  // (B, 3, 20)
    float* __restrict__ out)           // (B, 3, H, W)
{
    __shared__ ull sc2[3 * NCOEF];     // this batch's 60 splat pairs
    const int b = blockIdx.y;
    const int t = threadIdx.x;
    if (t < 3 * NCOEF) {
        ull u = (ull)__float_as_uint(coeffs[b * (3 * NCOEF) + t]);
        sc2[t] = u | (u << 32);        // splat {c, c}
    }
    __syncthreads();                   // the only barrier

    const int i0 = blockIdx.x * TPB + t;   // < 4608

    // One roving load pointer and one roving store pointer; every access is
    // at a compile-time immediate offset from them.
    const ulonglong2* __restrict__ pin =
        reinterpret_cast<const ulonglong2*>(img + (size_t)b * 3 * HW_PIX) + i0;
    ulonglong2* __restrict__ pout =
        reinterpret_cast<ulonglong2*>(out + (size_t)b * 3 * HW_PIX) + i0;

    // Prefetch first item (6 LDG.128, all immediate offsets).
    ulonglong2 a0 = pin[0],     a1 = pin[PLANE4],         a2 = pin[2 * PLANE4];
    ulonglong2 b0 = pin[HALF4], b1 = pin[HALF4 + PLANE4], b2 = pin[HALF4 + 2 * PLANE4];

    int i = i0;
#pragma unroll 1
    while (i < HALF4) {
        // Clamped next-pointer (uniform select): last iteration re-reads the
        // current item instead of running past the tensor for batch 15.
        const int inext = i + STRIDE;
        const ulonglong2* __restrict__ pn = (inext < HALF4) ? pin + STRIDE : pin;

        // Issue next item's 6 loads before computing (continuous MLP=6).
        const ulonglong2 na0 = pn[0],     na1 = pn[PLANE4],         na2 = pn[2 * PLANE4];
        const ulonglong2 nb0 = pn[HALF4], nb1 = pn[HALF4 + PLANE4], nb2 = pn[HALF4 + 2 * PLANE4];

#pragma unroll 1
        for (int oc = 0; oc < 3; oc++) {
            const ull* __restrict__ c = sc2 + oc * NCOEF;
            ulonglong2 ra, rb;
            ra.x = horner2(a0.x, a1.x, a2.x, c);
            ra.y = horner2(a0.y, a1.y, a2.y, c);
            rb.x = horner2(b0.x, b1.x, b2.x, c);
            rb.y = horner2(b0.y, b1.y, b2.y, c);
            // Immediate-offset stores relative to the roving store pointer.
            pout[(size_t)oc * PLANE4] = ra;
            pout[(size_t)oc * PLANE4 + HALF4] = rb;
        }

        // Rotate pipeline; bump pointers (2 x 64-bit adds).
        i = inext;
        pin = pn;
        pout += STRIDE;
        a0 = na0; a1 = na1; a2 = na2;
        b0 = nb0; b1 = nb1; b2 = nb2;
    }
}

extern "C" void kernel_launch(void* const* d_in, const int* in_sizes, int n_in,
                              void* d_out, int out_size) {
    const float* img = (const float*)d_in[0];     // (16,3,512,512)
    const float* coeffs = (const float*)d_in[1];  // (16,3,20)
    float* out = (float*)d_out;

    dim3 grid(CTAS_X, NBATCH, 1);                 // 18 x 16 = 288 CTAs
    channel_poly_kernel<<<grid, TPB>>>(img, coeffs, out);
}

// round 13
// speedup vs baseline: 1.0118x; 1.0118x over previous
#include <cuda_runtime.h>
#include <cuda_bf16.h>

// ChannelPolyLayer: out[b,o,x,y] = sum_c coeffs[b,o,c] * prod_v img[b,v,x,y]^powers[c,v]
// DEGREE=3, NUM_VARS=3, NUM_OUT=3, NUM_COEFFS=20, BATCH=16, H=W=512.
//
// Monomial order from _generate_powers(3,3):
//  0:1  1:v0  2:v1  3:v2  4:v0^2  5:v0v1  6:v0v2  7:v1^2  8:v1v2  9:v2^2
// 10:v0^3 11:v0^2v1 12:v0^2v2 13:v0v1^2 14:v0v1v2 15:v0v2^2
// 16:v1^3 17:v1^2v2 18:v1v2^2 19:v2^3
//
// Nested Horner, SCALAR fmaf (19 per output per pixel).
// R13 explores the untested quadrant: HIGH occupancy x CONTINUOUS prefetch.
// Scalar FFMA tolerates a tight reg cap (no FFMA2 operand-pairing pathology
// from R5): __launch_bounds__(256,5) = 48 regs -> 40 warps/SM, 1 float4
// item/thread with 1-deep prefetch (3 LDG.128 always outstanding).
// warps x continuous-MLP ~= 120 (vs 82 for the 16.9us champion).
// batch = blockIdx.y; grid 46x16 = 736 CTAs ~= one wave at 5 CTAs/SM.

#define HW_PIX (512 * 512)
#define PLANE4 (HW_PIX / 4)       // 65536 float4s per channel plane
#define NBATCH 16
#define NCOEF  20
#define TPB    256
#define CTAS_X 46                 // 46*16 = 736 CTAs ~= one wave at 5 CTAs/SM
#define STRIDE (CTAS_X * TPB)     // 11776

__device__ __forceinline__ float horner(float v0, float v1, float v2,
                                        const float* __restrict__ c) {
    // C0(v1,v2)
    float pA = fmaf(c[16], v1, c[7]);
    pA = fmaf(v1, pA, c[2]);
    pA = fmaf(v1, pA, c[0]);                 // c0 + c2 v1 + c7 v1^2 + c16 v1^3
    float pB = fmaf(c[17], v1, c[8]);
    pB = fmaf(v1, pB, c[3]);                 // c3 + c8 v1 + c17 v1^2
    float pC = fmaf(c[18], v1, c[9]);        // c9 + c18 v1
    float C0 = fmaf(c[19], v2, pC);
    C0 = fmaf(C0, v2, pB);
    C0 = fmaf(C0, v2, pA);
    // C1(v1,v2)
    float qA = fmaf(c[13], v1, c[5]);
    qA = fmaf(v1, qA, c[1]);                 // c1 + c5 v1 + c13 v1^2
    float qB = fmaf(c[14], v1, c[6]);        // c6 + c14 v1
    float C1 = fmaf(c[15], v2, qB);
    C1 = fmaf(C1, v2, qA);
    // C2(v1,v2)
    float C2 = fmaf(c[11], v1, c[4]);
    C2 = fmaf(c[12], v2, C2);
    // Horner in v0
    float r = fmaf(c[10], v0, C2);
    r = fmaf(r, v0, C1);
    r = fmaf(r, v0, C0);
    return r;
}

__global__ __launch_bounds__(TPB, 5) void channel_poly_kernel(
    const float* __restrict__ img,     // (B, 3, H, W)
    const float* __restrict__ coeffs,  // (B, 3, 20)
    float* __restrict__ out)           // (B, 3, H, W)
{
    __shared__ float sc[3 * NCOEF];    // this batch's 60 coefficients
    const int b = blockIdx.y;
    const int t = threadIdx.x;
    if (t < 3 * NCOEF) sc[t] = coeffs[b * (3 * NCOEF) + t];
    __syncthreads();                   // the only barrier

    const float4* __restrict__ in =
        reinterpret_cast<const float4*>(img + (size_t)b * 3 * HW_PIX);
    float4* __restrict__ op =
        reinterpret_cast<float4*>(out + (size_t)b * 3 * HW_PIX);

    int i = blockIdx.x * TPB + t;      // < 11776 < PLANE4 always

    // Prefetch first item (3 LDG.128).
    float4 x0 = in[i], x1 = in[i + PLANE4], x2 = in[i + 2 * PLANE4];

#pragma unroll 1
    while (i < PLANE4) {
        // Issue next item's 3 loads before computing this one
        // (keeps 3 LDG continuously outstanding per thread).
        const int inext = i + STRIDE;
        const int il = (inext < PLANE4) ? inext : i;  // safe addr; unused on tail
        const float4 n0 = in[il];
        const float4 n1 = in[il + PLANE4];
        const float4 n2 = in[il + 2 * PLANE4];

#pragma unroll 1
        for (int oc = 0; oc < 3; oc++) {
            const float* __restrict__ c = sc + oc * NCOEF;
            float4 r;
            r.x = horner(x0.x, x1.x, x2.x, c);
            r.y = horner(x0.y, x1.y, x2.y, c);
            r.z = horner(x0.z, x1.z, x2.z, c);
            r.w = horner(x0.w, x1.w, x2.w, c);
            op[i + oc * PLANE4] = r;
        }

        // Rotate pipeline.
        i = inext;
        x0 = n0; x1 = n1; x2 = n2;
    }
}

extern "C" void kernel_launch(void* const* d_in, const int* in_sizes, int n_in,
                              void* d_out, int out_size) {
    const float* img = (const float*)d_in[0];     // (16,3,512,512)
    const float* coeffs = (const float*)d_in[1];  // (16,3,20)
    float* out = (float*)d_out;

    dim3 grid(CTAS_X, NBATCH, 1);                 // 46 x 16 = 736 CTAs
    channel_poly_kernel<<<grid, TPB>>>(img, coeffs, out);
}